// round 6
// baseline (speedup 1.0000x reference)
#include <cuda_runtime.h>

#define B_ 256
#define T_ 1024
#define K_ 128

__device__ float g_denom[B_];
__device__ float g_num[B_];

typedef unsigned long long u64;

__device__ __forceinline__ void ffma2(u64 &d, u64 a, u64 b) {
    asm("fma.rn.f32x2 %0, %1, %2, %0;" : "+l"(d) : "l"(a), "l"(b));
}
__device__ __forceinline__ u64 fadd2(u64 a, u64 b) {
    u64 r; asm("add.rn.f32x2 %0, %1, %2;" : "=l"(r) : "l"(a), "l"(b)); return r;
}
__device__ __forceinline__ u64 pack2(float lo, float hi) {
    u64 r; asm("mov.b64 %0, {%1, %2};" : "=l"(r) : "f"(lo), "f"(hi)); return r;
}
__device__ __forceinline__ void unpack2(u64 v, float &lo, float &hi) {
    asm("mov.b64 {%0, %1}, %2;" : "=f"(lo), "=f"(hi) : "l"(v));
}

// ---------------------------------------------------------------------------
// Forward algorithm, exponential domain, critical-path minimized:
//   p'_j = (sum_i p_i E_ij) * exp(emit_j) * (1/p_0)
//   exp(emit) precomputed one step ahead; 1/p0 (MUFU.RCP) runs concurrently
//   with the FMA tree; log(p0) for the constant C is fully off-path.
// 256 thr/block: lane pair (2j,2j+1) owns state j, half h=tid&1 covers 64 i's.
// ---------------------------------------------------------------------------
__global__ void __launch_bounds__(256, 2) forward_kernel(
    const float* inp, const float* trans, const int* mask) {
    const int b   = blockIdx.x;
    const int tid = threadIdx.x;
    const int j   = tid >> 1;          // output state
    const int h   = tid & 1;           // i-half

    __shared__ __align__(16) float pbuf[2][K_];
    __shared__ int smask[T_];

    // mask row -> smem once (4 coalesced loads/thread)
#pragma unroll
    for (int t = tid; t < T_; t += 256) smask[t] = mask[(size_t)b * T_ + t];

    // E2[m] = pack(E[i], E[i+1]), i = 64h + 2m, column j.
    u64 E2[32];
#pragma unroll
    for (int m = 0; m < 32; m++) {
        const int i = (h << 6) + 2 * m;
        E2[m] = pack2(__expf(trans[i * K_ + j]),
                      __expf(trans[(i + 1) * K_ + j]));
    }

    const float* eb = inp + (size_t)b * T_ * K_;

    const float p_init = __expf(eb[j]);          // t = 0
    if (h == 0) pbuf[0][j] = p_init;
    float pcur = p_init;                         // register copy of p_j
    float C = 0.0f;
    __syncthreads();

    int cur = 0;
    float ee_next = __expf(eb[K_ + j]);          // exp(emit[1])

    for (int t = 1; t < T_; t++) {
        const float ee = ee_next;                // exp(emit[t]), ready
        const int   mc = smask[t];
        float e_raw = 0.0f;
        if (t + 1 < T_) e_raw = eb[(size_t)(t + 1) * K_ + j];

        const float p0  = pbuf[cur][0];          // LDS broadcast
        const float rp0 = __frcp_rn(p0);         // || with FMA tree
        const float lp0 = __logf(p0);            // off-path (feeds C only)

        const ulonglong2* pv = (const ulonglong2*)(pbuf[cur] + (h << 6));
        u64 acc[8];
#pragma unroll
        for (int q = 0; q < 8; q++) acc[q] = 0ULL;
#pragma unroll
        for (int k = 0; k < 16; k++) {
            const ulonglong2 u = pv[k];          // p[64h+4k .. +3]
            ffma2(acc[(2 * k)     & 7], u.x, E2[2 * k]);
            ffma2(acc[(2 * k + 1) & 7], u.y, E2[2 * k + 1]);
        }
        const u64 r = fadd2(fadd2(fadd2(acc[0], acc[1]), fadd2(acc[2], acc[3])),
                            fadd2(fadd2(acc[4], acc[5]), fadd2(acc[6], acc[7])));
        float lo, hi; unpack2(r, lo, hi);
        const float part = lo + hi;
        const float s = part + __shfl_xor_sync(0xffffffffu, part, 1);

        const float pn   = s * (ee * rp0);       // = s * exp(e - log p0)
        const float pnew = mc ? pn : pcur;       // masked step carries p
        C += mc ? lp0 : 0.0f;

        cur ^= 1;
        if (h == 0) pbuf[cur][j] = pnew;
        pcur = pnew;
        ee_next = __expf(e_raw);                 // for step t+1 (off-path)
        __syncthreads();
    }

    if (tid == 0) {
        float sum = 0.0f;                        // fixed order: deterministic
        for (int i = 0; i < K_; i++) sum += pbuf[cur][i];
        g_denom[b] = C + __logf(sum);
    }
}

// ---------------------------------------------------------------------------
// Joint (numerator) score. One block per batch, 128 threads strided over t.
// ---------------------------------------------------------------------------
__global__ void numerator_kernel(const float* inp, const float* trans,
                                 const int* tags, const int* mask) {
    const int b   = blockIdx.x;
    const int tid = threadIdx.x;       // 128
    const int*   tb = tags + (size_t)b * T_;
    const int*   mb = mask + (size_t)b * T_;
    const float* eb = inp  + (size_t)b * T_ * K_;

    float s = 0.0f;
    int msum = 0;
    for (int t = tid; t < T_; t += 128) {
        msum += mb[t];
        if (t < T_ - 1) {
            const int tg  = tb[t]     & (K_ - 1);
            const int tg1 = tb[t + 1] & (K_ - 1);
            s += trans[tg * K_ + tg1] * (float)mb[t + 1]
               + eb[(size_t)t * K_ + tg] * (float)mb[t];
        }
    }

    __shared__ float sf[128];
    __shared__ int   si[128];
    sf[tid] = s; si[tid] = msum;
    __syncthreads();
    for (int off = 64; off > 0; off >>= 1) {
        if (tid < off) { sf[tid] += sf[tid + off]; si[tid] += si[tid + off]; }
        __syncthreads();
    }
    if (tid == 0) {
        int last_idx = si[0] - 1;
        if (last_idx < 0)   last_idx = 0;
        if (last_idx >= T_) last_idx = T_ - 1;
        const int lt = tb[last_idx] & (K_ - 1);
        g_num[b] = sf[0]
                 + eb[(size_t)(T_ - 1) * K_ + lt] * (float)mb[T_ - 1];
    }
}

// ---------------------------------------------------------------------------
__global__ void final_kernel(float* out) {
    __shared__ float sd[B_];
    const int t = threadIdx.x;
    sd[t] = g_num[t] - g_denom[t];
    __syncthreads();
    for (int off = 128; off > 0; off >>= 1) {
        if (t < off) sd[t] += sd[t + off];
        __syncthreads();
    }
    if (t == 0) out[0] = sd[0];
}

// ---------------------------------------------------------------------------
extern "C" void kernel_launch(void* const* d_in, const int* in_sizes, int n_in,
                              void* d_out, int out_size) {
    const float* inp   = (const float*)d_in[0];   // (B,T,K) f32
    const float* trans = (const float*)d_in[1];   // (K,K)   f32
    const int*   tags  = (const int*)d_in[2];     // (B,T)   i32
    const int*   mask  = (const int*)d_in[3];     // (B,T)   i32
    float* out = (float*)d_out;

    forward_kernel<<<B_, 256>>>(inp, trans, mask);
    numerator_kernel<<<B_, 128>>>(inp, trans, tags, mask);
    final_kernel<<<1, B_>>>(out);
}

// round 8
// speedup vs baseline: 1.5811x; 1.5811x over previous
#include <cuda_runtime.h>

#define B_ 256
#define T_ 1024
#define K_ 128

__device__ float g_denom[B_];
__device__ float g_num[B_];

typedef unsigned long long u64;

__device__ __forceinline__ void ffma2(u64 &d, u64 a, u64 b) {
    asm("fma.rn.f32x2 %0, %1, %2, %0;" : "+l"(d) : "l"(a), "l"(b));
}
__device__ __forceinline__ u64 fadd2(u64 a, u64 b) {
    u64 r; asm("add.rn.f32x2 %0, %1, %2;" : "=l"(r) : "l"(a), "l"(b)); return r;
}
__device__ __forceinline__ u64 pack2(float lo, float hi) {
    u64 r; asm("mov.b64 %0, {%1, %2};" : "=l"(r) : "f"(lo), "f"(hi)); return r;
}
__device__ __forceinline__ void unpack2(u64 v, float &lo, float &hi) {
    asm("mov.b64 {%0, %1}, %2;" : "=f"(lo), "=f"(hi) : "l"(v));
}

// ---------------------------------------------------------------------------
// Forward algorithm, exponential domain:
//   p'_j = (sum_i p_i E_ij) * exp(emit_j) * (1/p_0);  C += log(p_0)
// 128 thr/block, thread j owns state j, FULL i-range per thread:
// 32 broadcast LDS.128 (conflict-free) + 64 packed f32x2 FMAs per step.
// Emission pipeline two deep (load t+2, exp t+1): global latency and the exp
// are both off the recurrence path. rcp(p0) runs concurrently with the FMA
// tree; log(p0) feeds only C. Double-buffered p, one barrier per step.
// ---------------------------------------------------------------------------
__global__ void __launch_bounds__(128, 2) forward_kernel(
    const float* inp, const float* trans, const int* mask) {
    const int b = blockIdx.x;
    const int j = threadIdx.x;          // output state

    __shared__ __align__(16) float pbuf[2][K_];
    __shared__ int smask[T_];

    for (int t = j; t < T_; t += 128) smask[t] = mask[(size_t)b * T_ + t];

    // E2[m] = pack(E[2m][j], E[2m+1][j]) — column j as 64 packed pairs.
    u64 E2[64];
#pragma unroll
    for (int m = 0; m < 64; m++)
        E2[m] = pack2(__expf(trans[(2 * m) * K_ + j]),
                      __expf(trans[(2 * m + 1) * K_ + j]));

    const float* eb = inp + (size_t)b * T_ * K_;

    const float p_init = __expf(eb[j]);       // t = 0
    pbuf[0][j] = p_init;
    float pcur = p_init;
    float C = 0.0f;

    float ee = __expf(eb[K_ + j]);            // exp(emit[1])   (for t = 1)
    float er = eb[2 * K_ + j];                // raw emit[2]    (for t = 2)
    __syncthreads();

    int cur = 0;
    for (int t = 1; t < T_; t++) {
        // pipeline refills (consumed one and two steps later)
        const float er2 = (t + 2 < T_) ? eb[(size_t)(t + 2) * K_ + j] : 0.0f;
        const float ee2 = __expf(er);         // exp(emit[t+1]); er is ready

        const int   mc  = smask[t];
        const float p0  = pbuf[cur][0];       // broadcast
        const float rp0 = __frcp_rn(p0);      // MUFU, parallel w/ FMA tree
        const float lp0 = __logf(p0);         // off-path (feeds C only)

        const ulonglong2* pv = (const ulonglong2*)pbuf[cur];
        u64 acc[8];
#pragma unroll
        for (int q = 0; q < 8; q++) acc[q] = 0ULL;
#pragma unroll
        for (int k = 0; k < 32; k++) {        // FULL range: p[0..127]
            const ulonglong2 u = pv[k];       // p[4k..4k+3], broadcast LDS.128
            ffma2(acc[(2 * k)     & 7], u.x, E2[2 * k]);
            ffma2(acc[(2 * k + 1) & 7], u.y, E2[2 * k + 1]);
        }
        const u64 r = fadd2(fadd2(fadd2(acc[0], acc[1]), fadd2(acc[2], acc[3])),
                            fadd2(fadd2(acc[4], acc[5]), fadd2(acc[6], acc[7])));
        float lo, hi; unpack2(r, lo, hi);
        const float s = lo + hi;              // s_j = sum_i p_i E_ij

        const float pn   = s * (ee * rp0);    // = s * exp(emit - log p0)
        const float pnew = mc ? pn : pcur;    // masked step carries p
        C += mc ? lp0 : 0.0f;

        cur ^= 1;
        pbuf[cur][j] = pnew;
        pcur = pnew;
        __syncthreads();                      // one barrier per step

        ee = ee2; er = er2;                   // rotate pipeline
    }

    if (j == 0) {
        float sum = 0.0f;                     // fixed order: deterministic
        for (int i = 0; i < K_; i++) sum += pbuf[cur][i];
        g_denom[b] = C + __logf(sum);
    }
}

// ---------------------------------------------------------------------------
// Joint (numerator) score. One block per batch, 128 threads strided over t.
// ---------------------------------------------------------------------------
__global__ void numerator_kernel(const float* inp, const float* trans,
                                 const int* tags, const int* mask) {
    const int b   = blockIdx.x;
    const int tid = threadIdx.x;        // 128
    const int*   tb = tags + (size_t)b * T_;
    const int*   mb = mask + (size_t)b * T_;
    const float* eb = inp  + (size_t)b * T_ * K_;

    float s = 0.0f;
    int msum = 0;
    for (int t = tid; t < T_; t += 128) {
        msum += mb[t];
        if (t < T_ - 1) {
            const int tg  = tb[t]     & (K_ - 1);
            const int tg1 = tb[t + 1] & (K_ - 1);
            s += trans[tg * K_ + tg1] * (float)mb[t + 1]
               + eb[(size_t)t * K_ + tg] * (float)mb[t];
        }
    }

    __shared__ float sf[128];
    __shared__ int   si[128];
    sf[tid] = s; si[tid] = msum;
    __syncthreads();
    for (int off = 64; off > 0; off >>= 1) {
        if (tid < off) { sf[tid] += sf[tid + off]; si[tid] += si[tid + off]; }
        __syncthreads();
    }
    if (tid == 0) {
        int last_idx = si[0] - 1;
        if (last_idx < 0)   last_idx = 0;
        if (last_idx >= T_) last_idx = T_ - 1;
        const int lt = tb[last_idx] & (K_ - 1);
        g_num[b] = sf[0]
                 + eb[(size_t)(T_ - 1) * K_ + lt] * (float)mb[T_ - 1];
    }
}

// ---------------------------------------------------------------------------
__global__ void final_kernel(float* out) {
    __shared__ float sd[B_];
    const int t = threadIdx.x;
    sd[t] = g_num[t] - g_denom[t];
    __syncthreads();
    for (int off = 128; off > 0; off >>= 1) {
        if (t < off) sd[t] += sd[t + off];
        __syncthreads();
    }
    if (t == 0) out[0] = sd[0];
}

// ---------------------------------------------------------------------------
extern "C" void kernel_launch(void* const* d_in, const int* in_sizes, int n_in,
                              void* d_out, int out_size) {
    const float* inp   = (const float*)d_in[0];   // (B,T,K) f32
    const float* trans = (const float*)d_in[1];   // (K,K)   f32
    const int*   tags  = (const int*)d_in[2];     // (B,T)   i32
    const int*   mask  = (const int*)d_in[3];     // (B,T)   i32
    float* out = (float*)d_out;

    forward_kernel<<<B_, 128>>>(inp, trans, mask);
    numerator_kernel<<<B_, 128>>>(inp, trans, tags, mask);
    final_kernel<<<1, B_>>>(out);
}

// round 9
// speedup vs baseline: 2.1126x; 1.3361x over previous
#include <cuda_runtime.h>

#define B_ 256
#define T_ 1024
#define K_ 128

__device__ float g_denom[B_];
__device__ float g_num[B_];

typedef unsigned long long u64;

__device__ __forceinline__ void ffma2(u64 &d, u64 a, u64 b) {
    asm("fma.rn.f32x2 %0, %1, %2, %0;" : "+l"(d) : "l"(a), "l"(b));
}
__device__ __forceinline__ u64 fadd2(u64 a, u64 b) {
    u64 r; asm("add.rn.f32x2 %0, %1, %2;" : "=l"(r) : "l"(a), "l"(b)); return r;
}
__device__ __forceinline__ u64 pack2(float lo, float hi) {
    u64 r; asm("mov.b64 %0, {%1, %2};" : "=l"(r) : "f"(lo), "f"(hi)); return r;
}
__device__ __forceinline__ void unpack2(u64 v, float &lo, float &hi) {
    asm("mov.b64 {%0, %1}, %2;" : "=f"(lo), "=f"(hi) : "l"(v));
}

// ---------------------------------------------------------------------------
// Forward algorithm, exponential domain:
//   p'_j = (sum_i p_i E_ij) * exp(emit_j) * (1/p_0);  C += log(p_0)
// 128 thr/block, thread j owns state j, full i-range per thread.
// KEY CHANGE vs R8: the emission stream is DRAM-latency paced at MLP=1 with
// only 1 step of slack. Now a 4-deep register ring (r1..r4) gives the LDG
// 4 full steps to complete; exp applied one step before use. The recurrence
// step is then bounded by compute/issue, not by DRAM latency.
// ---------------------------------------------------------------------------
__global__ void __launch_bounds__(128, 2) forward_kernel(
    const float* inp, const float* trans, const int* mask) {
    const int b = blockIdx.x;
    const int j = threadIdx.x;          // output state

    __shared__ __align__(16) float pbuf[2][K_];
    __shared__ int smask[T_];

    for (int t = j; t < T_; t += 128) smask[t] = mask[(size_t)b * T_ + t];

    // E2[m] = pack(E[2m][j], E[2m+1][j]) — column j as 64 packed pairs.
    u64 E2[64];
#pragma unroll
    for (int m = 0; m < 64; m++)
        E2[m] = pack2(__expf(trans[(2 * m) * K_ + j]),
                      __expf(trans[(2 * m + 1) * K_ + j]));

    const float* eb = inp + (size_t)b * T_ * K_;

    const float p_init = __expf(eb[j]);       // t = 0
    pbuf[0][j] = p_init;
    float pcur = p_init;
    float C = 0.0f;

    // Emission pipeline: ee = exp(emit[t]) for current step; r1..r4 hold raw
    // emit[t+1..t+4]. Value loaded at step u-5 is exp'd at u-1, used at u.
    float ee = __expf(eb[K_ + j]);            // exp(emit[1])
    float r1 = eb[2 * K_ + j];                // emit[2]
    float r2 = eb[3 * K_ + j];                // emit[3]
    float r3 = eb[4 * K_ + j];                // emit[4]
    float r4 = eb[5 * K_ + j];                // emit[5]
    __syncthreads();

    int cur = 0;
    for (int t = 1; t < T_; t++) {
        // refill: load emit[t+5] (consumed 4 steps from now)
        const float rnew = (t + 5 < T_) ? eb[(size_t)(t + 5) * K_ + j] : 0.0f;
        const float ee2  = __expf(r1);        // exp(emit[t+1]); r1 aged 4 steps

        const int   mc  = smask[t];
        const float p0  = pbuf[cur][0];       // broadcast
        const float rp0 = __frcp_rn(p0);      // MUFU, parallel w/ FMA tree
        const float lp0 = __logf(p0);         // off-path (feeds C only)

        const ulonglong2* pv = (const ulonglong2*)pbuf[cur];
        u64 acc[8];
#pragma unroll
        for (int q = 0; q < 8; q++) acc[q] = 0ULL;
#pragma unroll
        for (int k = 0; k < 32; k++) {        // full range: p[0..127]
            const ulonglong2 u = pv[k];       // p[4k..4k+3], broadcast LDS.128
            ffma2(acc[(2 * k)     & 7], u.x, E2[2 * k]);
            ffma2(acc[(2 * k + 1) & 7], u.y, E2[2 * k + 1]);
        }
        const u64 r = fadd2(fadd2(fadd2(acc[0], acc[1]), fadd2(acc[2], acc[3])),
                            fadd2(fadd2(acc[4], acc[5]), fadd2(acc[6], acc[7])));
        float lo, hi; unpack2(r, lo, hi);
        const float s = lo + hi;              // s_j = sum_i p_i E_ij

        const float pn   = s * (ee * rp0);    // = s * exp(emit - log p0)
        const float pnew = mc ? pn : pcur;    // masked step carries p
        C += mc ? lp0 : 0.0f;

        cur ^= 1;
        pbuf[cur][j] = pnew;
        pcur = pnew;
        __syncthreads();                      // one barrier per step

        ee = ee2;                             // rotate pipeline
        r1 = r2; r2 = r3; r3 = r4; r4 = rnew;
    }

    if (j == 0) {
        float sum = 0.0f;                     // fixed order: deterministic
        for (int i = 0; i < K_; i++) sum += pbuf[cur][i];
        g_denom[b] = C + __logf(sum);
    }
}

// ---------------------------------------------------------------------------
// Joint (numerator) score. One block per batch, 128 threads strided over t.
// ---------------------------------------------------------------------------
__global__ void numerator_kernel(const float* inp, const float* trans,
                                 const int* tags, const int* mask) {
    const int b   = blockIdx.x;
    const int tid = threadIdx.x;        // 128
    const int*   tb = tags + (size_t)b * T_;
    const int*   mb = mask + (size_t)b * T_;
    const float* eb = inp  + (size_t)b * T_ * K_;

    float s = 0.0f;
    int msum = 0;
    for (int t = tid; t < T_; t += 128) {
        msum += mb[t];
        if (t < T_ - 1) {
            const int tg  = tb[t]     & (K_ - 1);
            const int tg1 = tb[t + 1] & (K_ - 1);
            s += trans[tg * K_ + tg1] * (float)mb[t + 1]
               + eb[(size_t)t * K_ + tg] * (float)mb[t];
        }
    }

    __shared__ float sf[128];
    __shared__ int   si[128];
    sf[tid] = s; si[tid] = msum;
    __syncthreads();
    for (int off = 64; off > 0; off >>= 1) {
        if (tid < off) { sf[tid] += sf[tid + off]; si[tid] += si[tid + off]; }
        __syncthreads();
    }
    if (tid == 0) {
        int last_idx = si[0] - 1;
        if (last_idx < 0)   last_idx = 0;
        if (last_idx >= T_) last_idx = T_ - 1;
        const int lt = tb[last_idx] & (K_ - 1);
        g_num[b] = sf[0]
                 + eb[(size_t)(T_ - 1) * K_ + lt] * (float)mb[T_ - 1];
    }
}

// ---------------------------------------------------------------------------
__global__ void final_kernel(float* out) {
    __shared__ float sd[B_];
    const int t = threadIdx.x;
    sd[t] = g_num[t] - g_denom[t];
    __syncthreads();
    for (int off = 128; off > 0; off >>= 1) {
        if (t < off) sd[t] += sd[t + off];
        __syncthreads();
    }
    if (t == 0) out[0] = sd[0];
}

// ---------------------------------------------------------------------------
extern "C" void kernel_launch(void* const* d_in, const int* in_sizes, int n_in,
                              void* d_out, int out_size) {
    const float* inp   = (const float*)d_in[0];   // (B,T,K) f32
    const float* trans = (const float*)d_in[1];   // (K,K)   f32
    const int*   tags  = (const int*)d_in[2];     // (B,T)   i32
    const int*   mask  = (const int*)d_in[3];     // (B,T)   i32
    float* out = (float*)d_out;

    forward_kernel<<<B_, 128>>>(inp, trans, mask);
    numerator_kernel<<<B_, 128>>>(inp, trans, tags, mask);
    final_kernel<<<1, B_>>>(out);
}